// round 5
// baseline (speedup 1.0000x reference)
#include <cuda_runtime.h>
#include <cuda_bf16.h>
#include <cstdint>

// Problem constants
#define BB 8
#define CC 256
#define HH 128
#define WW 128
#define ND 64

// ---------------------------------------------------------------------------
// Scratch (__device__ globals; no runtime allocation)
// ---------------------------------------------------------------------------
__device__ float g_style[BB * CC];
__device__ __align__(256) __nv_bfloat16 g_Ahi[BB * 9 * CC * CC];   // [b][tap][oc][i]
__device__ __align__(256) __nv_bfloat16 g_Alo[BB * 9 * CC * CC];
__device__ __align__(256) __nv_bfloat16 g_Fhi[(size_t)BB * HH * WW * CC];  // [b][y][x][c]
__device__ __align__(256) __nv_bfloat16 g_Flo[(size_t)BB * HH * WW * CC];

// ---------------------------------------------------------------------------
// PTX helpers (sm_80-era; compile on compute_103)
// ---------------------------------------------------------------------------
__device__ __forceinline__ uint32_t smem_u32(const void* p) {
    uint32_t a;
    asm("{ .reg .u64 t; cvta.to.shared.u64 t, %1; cvt.u32.u64 %0, t; }" : "=r"(a) : "l"(p));
    return a;
}
__device__ __forceinline__ void cpa16(uint32_t dst, const void* src, uint32_t bytes) {
    asm volatile("cp.async.cg.shared.global [%0], [%1], 16, %2;"
                 :: "r"(dst), "l"(src), "r"(bytes) : "memory");
}
__device__ __forceinline__ void cpa_commit() {
    asm volatile("cp.async.commit_group;" ::: "memory");
}
__device__ __forceinline__ void cpa_wait2() {
    asm volatile("cp.async.wait_group 2;" ::: "memory");
}
__device__ __forceinline__ uint32_t swz(uint32_t off) { return off ^ ((off >> 3) & 0x70); }

__device__ __forceinline__ void ldsm_x4(uint32_t& r0, uint32_t& r1, uint32_t& r2, uint32_t& r3,
                                        uint32_t addr) {
    asm volatile("ldmatrix.sync.aligned.m8n8.x4.shared.b16 {%0,%1,%2,%3}, [%4];"
                 : "=r"(r0), "=r"(r1), "=r"(r2), "=r"(r3) : "r"(addr));
}
__device__ __forceinline__ void mma_bf16(float* d, const uint32_t* a, const uint32_t* b) {
    asm volatile(
        "mma.sync.aligned.m16n8k16.row.col.f32.bf16.bf16.f32 "
        "{%0,%1,%2,%3}, {%4,%5,%6,%7}, {%8,%9}, {%0,%1,%2,%3};"
        : "+f"(d[0]), "+f"(d[1]), "+f"(d[2]), "+f"(d[3])
        : "r"(a[0]), "r"(a[1]), "r"(a[2]), "r"(a[3]), "r"(b[0]), "r"(b[1]));
}

// ---------------------------------------------------------------------------
// Kernel 0: style
// ---------------------------------------------------------------------------
__global__ void style_kernel(const float* __restrict__ nf,
                             const float* __restrict__ mw,
                             const float* __restrict__ mb) {
    int b = blockIdx.x, c = threadIdx.x;
    const float* nfb = nf + b * ND;
    const float* mwc = mw + c * ND;
    float s = 0.f;
#pragma unroll
    for (int d = 0; d < ND; ++d) s += nfb[d] * mwc[d];
    g_style[b * CC + c] = s + mb[c];
}

// ---------------------------------------------------------------------------
// Kernel 1: modulate + demod weights, split bf16, layout [b][tap][oc][i]
// ---------------------------------------------------------------------------
__global__ void modw_kernel(const float* __restrict__ weight) {
    int o = blockIdx.x, b = blockIdx.y, i = threadIdx.x;
    const float scale = 1.0f / 48.0f;
    float s = g_style[b * CC + i] * scale;
    const float* wp = weight + (o * CC + i) * 9;
    float v[9];
    float sq = 0.f;
#pragma unroll
    for (int k = 0; k < 9; ++k) { v[k] = wp[k] * s; sq += v[k] * v[k]; }

    __shared__ float red[8];
#pragma unroll
    for (int off = 16; off; off >>= 1) sq += __shfl_xor_sync(0xffffffffu, sq, off);
    if ((threadIdx.x & 31) == 0) red[threadIdx.x >> 5] = sq;
    __syncthreads();
    if (threadIdx.x < 8) {
        float t = red[threadIdx.x];
#pragma unroll
        for (int off = 4; off; off >>= 1) t += __shfl_xor_sync(0xffu, t, off);
        if (threadIdx.x == 0) red[0] = t;
    }
    __syncthreads();
    float demod = rsqrtf(red[0] + 1e-8f);
#pragma unroll
    for (int k = 0; k < 9; ++k) {
        float val = v[k] * demod;
        __nv_bfloat16 hi = __float2bfloat16(val);
        float lof = val - __bfloat162float(hi);
        size_t idx = ((size_t)((b * 9 + k) * CC) + o) * CC + i;
        g_Ahi[idx] = hi;
        g_Alo[idx] = __float2bfloat16(lof);
    }
}

// ---------------------------------------------------------------------------
// Kernel 2: fea NCHW -> [b][y][x][c] with bf16 hi/lo split
// ---------------------------------------------------------------------------
__global__ __launch_bounds__(256)
void tsplit_kernel(const float* __restrict__ fea) {
    int y = blockIdx.x, b = blockIdx.y;
    __shared__ float t[64][129];
    for (int cc = 0; cc < 4; ++cc) {
#pragma unroll
        for (int k = 0; k < 32; ++k) {
            int idx = threadIdx.x + k * 256;
            int cs = idx >> 7, x = idx & 127;
            t[cs][x] = fea[(((size_t)(b * CC + cc * 64 + cs)) * HH + y) * WW + x];
        }
        __syncthreads();
#pragma unroll
        for (int k = 0; k < 32; ++k) {
            int idx = threadIdx.x + k * 256;
            int c2 = idx & 63, x = idx >> 6;
            float v = t[c2][x];
            __nv_bfloat16 hi = __float2bfloat16(v);
            size_t o = ((size_t)((b * HH + y) * WW + x)) * CC + cc * 64 + c2;
            g_Fhi[o] = hi;
            g_Flo[o] = __float2bfloat16(v - __bfloat162float(hi));
        }
        __syncthreads();
    }
}

// ---------------------------------------------------------------------------
// Kernel 3: implicit-GEMM conv via mma.sync (split-bf16, 3 terms)
// grid (y=128, mtile=2, b=8); 512 threads = 16 warps (4M x 4N), warp tile 32x32
// K-loop: 36 steps = 9 taps x 4 chunks of 64 ch; 3-stage cp.async ring.
// Stage layout (64KB): Ah@0 Al@16K Bh@32K Bl@48K; each 128 rows x 128B, SW128.
// ---------------------------------------------------------------------------
#define NSTAGE 3
#define STAGE_BYTES 65536
#define SMEM_TOTAL (NSTAGE * STAGE_BYTES)

__global__ __launch_bounds__(512, 1)
void gemm_kernel(float* __restrict__ out) {
    extern __shared__ char smem[];
    const uint32_t sb = smem_u32(smem);
    const int tid  = threadIdx.x;
    const int lane = tid & 31;
    const int wid  = tid >> 5;
    const int warpM = wid >> 2;   // 0..3 (32 oc rows each)
    const int warpN = wid & 3;    // 0..3 (32 x cols each)
    const int y = blockIdx.x, mt = blockIdx.y, b = blockIdx.z;

    // ---- producer constants: each thread owns one 128B row of one operand ----
    const int op  = tid >> 7;       // 0=Ah 1=Al 2=Bh 3=Bl
    const int row = tid & 127;      // oc row (A) or pixel (B)
    const uint32_t dstoff = (uint32_t)op * 16384u;
    const size_t abase = ((size_t)(b * 9) * CC + (size_t)mt * 128 + row) * CC;

    auto issue = [&](int step, int buf) {
        const int tap = step >> 2, ck = step & 3;
        const uint32_t stg = sb + (uint32_t)buf * STAGE_BYTES + dstoff;
        const char* src;
        uint32_t bytes = 16u;
        if (op < 2) {
            const size_t aoff = abase + (size_t)tap * CC * CC + ck * 64;
            src = (const char*)((op == 0 ? g_Ahi : g_Alo) + aoff);
        } else {
            const int yy = y + tap / 3 - 1;
            const int xx = row + tap % 3 - 1;
            const bool bv = (yy >= 0 && yy < HH && xx >= 0 && xx < WW);
            const size_t boff =
                ((size_t)((b * HH + (bv ? yy : 0)) * WW + (bv ? xx : 0))) * CC + ck * 64;
            src = (const char*)((op == 2 ? g_Fhi : g_Flo) + boff);
            bytes = bv ? 16u : 0u;
        }
#pragma unroll
        for (int j = 0; j < 8; ++j)
            cpa16(stg + swz((uint32_t)row * 128u + j * 16u), src + j * 16, bytes);
    };

    // ---- consumer address bases (pre-swizzle offsets within a stage) ----
    // A (x4): row = warpM*32 + m*16 + (lane&15); col16B = (lane>>4)
    const uint32_t aRowB = ((uint32_t)warpM * 32u + (lane & 15)) * 128u + ((lane >> 4) * 16u);
    // B (x4, two n-tiles): row = warpN*32 + np*16 + (lane>>4)*8 + (lane&7); col16B = ((lane>>3)&1)
    const uint32_t bRowB = ((uint32_t)warpN * 32u + (lane >> 4) * 8u + (lane & 7)) * 128u
                           + (((lane >> 3) & 1) * 16u);

    float acc[2][4][4];
#pragma unroll
    for (int m = 0; m < 2; ++m)
#pragma unroll
        for (int n = 0; n < 4; ++n)
#pragma unroll
            for (int i = 0; i < 4; ++i) acc[m][n][i] = 0.f;

    issue(0, 0); cpa_commit();
    issue(1, 1); cpa_commit();

#pragma unroll 1
    for (int s = 0; s < 36; ++s) {
        if (s + 2 < 36) issue(s + 2, (s + 2) % NSTAGE);
        cpa_commit();
        cpa_wait2();
        __syncthreads();

        const uint32_t stg = sb + (uint32_t)(s % NSTAGE) * STAGE_BYTES;

#pragma unroll
        for (int kk = 0; kk < 4; ++kk) {
            uint32_t Ah[2][4], Al[2][4], Bh[2][4], Bl[2][4];
#pragma unroll
            for (int m = 0; m < 2; ++m) {
                const uint32_t off = swz(aRowB + (uint32_t)m * 2048u + (uint32_t)kk * 32u);
                ldsm_x4(Ah[m][0], Ah[m][1], Ah[m][2], Ah[m][3], stg + off);
                ldsm_x4(Al[m][0], Al[m][1], Al[m][2], Al[m][3], stg + 16384u + off);
            }
#pragma unroll
            for (int np = 0; np < 2; ++np) {   // each x4 covers n-tiles 2np, 2np+1
                const uint32_t off = swz(bRowB + (uint32_t)np * 2048u + (uint32_t)kk * 32u);
                ldsm_x4(Bh[np][0], Bh[np][1], Bh[np][2], Bh[np][3], stg + 32768u + off);
                ldsm_x4(Bl[np][0], Bl[np][1], Bl[np][2], Bl[np][3], stg + 49152u + off);
            }
#pragma unroll
            for (int m = 0; m < 2; ++m)
#pragma unroll
                for (int n = 0; n < 4; ++n) {
                    const uint32_t* bh = &Bh[n >> 1][(n & 1) * 2];
                    const uint32_t* bl = &Bl[n >> 1][(n & 1) * 2];
                    mma_bf16(acc[m][n], Ah[m], bh);
                    mma_bf16(acc[m][n], Ah[m], bl);
                    mma_bf16(acc[m][n], Al[m], bh);
                }
        }
        __syncthreads();
    }

    // ---- epilogue ----
    const int r0 = mt * 128 + warpM * 32 + (lane >> 2);
    const int xc = warpN * 32 + (lane & 3) * 2;
#pragma unroll
    for (int m = 0; m < 2; ++m) {
#pragma unroll
        for (int n = 0; n < 4; ++n) {
            float* p0 = out + (((size_t)(b * CC + r0 + m * 16) * HH + y) * WW) + xc + n * 8;
            float* p1 = p0 + (size_t)8 * HH * WW;
            *(float2*)p0 = make_float2(acc[m][n][0], acc[m][n][1]);
            *(float2*)p1 = make_float2(acc[m][n][2], acc[m][n][3]);
        }
    }
}

// ---------------------------------------------------------------------------
extern "C" void kernel_launch(void* const* d_in, const int* in_sizes, int n_in,
                              void* d_out, int out_size) {
    const float* fea    = (const float*)d_in[0];
    const float* nf     = (const float*)d_in[1];
    const float* mw     = (const float*)d_in[2];
    const float* mb     = (const float*)d_in[3];
    const float* weight = (const float*)d_in[4];
    float* out = (float*)d_out;

    cudaFuncSetAttribute(gemm_kernel, cudaFuncAttributeMaxDynamicSharedMemorySize, SMEM_TOTAL);

    style_kernel<<<BB, CC>>>(nf, mw, mb);
    modw_kernel<<<dim3(CC, BB), CC>>>(weight);
    tsplit_kernel<<<dim3(HH, BB), 256>>>(fea);
    gemm_kernel<<<dim3(HH, 2, BB), 512, SMEM_TOTAL>>>(out);
}

// round 6
// speedup vs baseline: 1.2085x; 1.2085x over previous
#include <cuda_runtime.h>
#include <cuda_bf16.h>
#include <cstdint>

// Problem constants
#define BB 8
#define CC 256
#define HH 128
#define WW 128
#define ND 64

// ---------------------------------------------------------------------------
// Scratch (__device__ globals; no runtime allocation)
// ---------------------------------------------------------------------------
__device__ float g_style[BB * CC];
__device__ __align__(256) __nv_bfloat16 g_Ahi[BB * 9 * CC * CC];   // [b][tap][oc][i]
__device__ __align__(256) __nv_bfloat16 g_Alo[BB * 9 * CC * CC];
__device__ __align__(256) __nv_bfloat16 g_Fhi[(size_t)BB * HH * WW * CC];  // [b][y][x][c]
__device__ __align__(256) __nv_bfloat16 g_Flo[(size_t)BB * HH * WW * CC];

// ---------------------------------------------------------------------------
// PTX helpers (sm_80-era; compile on compute_103)
// ---------------------------------------------------------------------------
__device__ __forceinline__ uint32_t smem_u32(const void* p) {
    uint32_t a;
    asm("{ .reg .u64 t; cvta.to.shared.u64 t, %1; cvt.u32.u64 %0, t; }" : "=r"(a) : "l"(p));
    return a;
}
__device__ __forceinline__ void cpa16(uint32_t dst, const void* src, uint32_t bytes) {
    asm volatile("cp.async.cg.shared.global [%0], [%1], 16, %2;"
                 :: "r"(dst), "l"(src), "r"(bytes) : "memory");
}
__device__ __forceinline__ void cpa_commit() {
    asm volatile("cp.async.commit_group;" ::: "memory");
}
__device__ __forceinline__ void cpa_wait1() {
    asm volatile("cp.async.wait_group 1;" ::: "memory");
}
__device__ __forceinline__ uint32_t swz(uint32_t off) { return off ^ ((off >> 3) & 0x70); }

__device__ __forceinline__ void ldsm_x4(uint32_t& r0, uint32_t& r1, uint32_t& r2, uint32_t& r3,
                                        uint32_t addr) {
    asm volatile("ldmatrix.sync.aligned.m8n8.x4.shared.b16 {%0,%1,%2,%3}, [%4];"
                 : "=r"(r0), "=r"(r1), "=r"(r2), "=r"(r3) : "r"(addr));
}
__device__ __forceinline__ void mma_bf16(float* d, const uint32_t* a, const uint32_t* b) {
    asm volatile(
        "mma.sync.aligned.m16n8k16.row.col.f32.bf16.bf16.f32 "
        "{%0,%1,%2,%3}, {%4,%5,%6,%7}, {%8,%9}, {%0,%1,%2,%3};"
        : "+f"(d[0]), "+f"(d[1]), "+f"(d[2]), "+f"(d[3])
        : "r"(a[0]), "r"(a[1]), "r"(a[2]), "r"(a[3]), "r"(b[0]), "r"(b[1]));
}

// ---------------------------------------------------------------------------
// Kernel 0: style
// ---------------------------------------------------------------------------
__global__ void style_kernel(const float* __restrict__ nf,
                             const float* __restrict__ mw,
                             const float* __restrict__ mb) {
    int b = blockIdx.x, c = threadIdx.x;
    const float* nfb = nf + b * ND;
    const float* mwc = mw + c * ND;
    float s = 0.f;
#pragma unroll
    for (int d = 0; d < ND; ++d) s += nfb[d] * mwc[d];
    g_style[b * CC + c] = s + mb[c];
}

// ---------------------------------------------------------------------------
// Kernel 1: modulate + demod weights, split bf16, layout [b][tap][oc][i]
// ---------------------------------------------------------------------------
__global__ void modw_kernel(const float* __restrict__ weight) {
    int o = blockIdx.x, b = blockIdx.y, i = threadIdx.x;
    const float scale = 1.0f / 48.0f;
    float s = g_style[b * CC + i] * scale;
    const float* wp = weight + (o * CC + i) * 9;
    float v[9];
    float sq = 0.f;
#pragma unroll
    for (int k = 0; k < 9; ++k) { v[k] = wp[k] * s; sq += v[k] * v[k]; }

    __shared__ float red[8];
#pragma unroll
    for (int off = 16; off; off >>= 1) sq += __shfl_xor_sync(0xffffffffu, sq, off);
    if ((threadIdx.x & 31) == 0) red[threadIdx.x >> 5] = sq;
    __syncthreads();
    if (threadIdx.x < 8) {
        float t = red[threadIdx.x];
#pragma unroll
        for (int off = 4; off; off >>= 1) t += __shfl_xor_sync(0xffu, t, off);
        if (threadIdx.x == 0) red[0] = t;
    }
    __syncthreads();
    float demod = rsqrtf(red[0] + 1e-8f);
#pragma unroll
    for (int k = 0; k < 9; ++k) {
        float val = v[k] * demod;
        __nv_bfloat16 hi = __float2bfloat16(val);
        float lof = val - __bfloat162float(hi);
        size_t idx = ((size_t)((b * 9 + k) * CC) + o) * CC + i;
        g_Ahi[idx] = hi;
        g_Alo[idx] = __float2bfloat16(lof);
    }
}

// ---------------------------------------------------------------------------
// Kernel 2: fea NCHW -> [b][y][x][c] with bf16 hi/lo split
// ---------------------------------------------------------------------------
__global__ __launch_bounds__(256)
void tsplit_kernel(const float* __restrict__ fea) {
    int y = blockIdx.x, b = blockIdx.y;
    __shared__ float t[64][129];
    for (int cc = 0; cc < 4; ++cc) {
#pragma unroll
        for (int k = 0; k < 32; ++k) {
            int idx = threadIdx.x + k * 256;
            int cs = idx >> 7, x = idx & 127;
            t[cs][x] = fea[(((size_t)(b * CC + cc * 64 + cs)) * HH + y) * WW + x];
        }
        __syncthreads();
#pragma unroll
        for (int k = 0; k < 32; ++k) {
            int idx = threadIdx.x + k * 256;
            int c2 = idx & 63, x = idx >> 6;
            float v = t[c2][x];
            __nv_bfloat16 hi = __float2bfloat16(v);
            size_t o = ((size_t)((b * HH + y) * WW + x)) * CC + cc * 64 + c2;
            g_Fhi[o] = hi;
            g_Flo[o] = __float2bfloat16(v - __bfloat162float(hi));
        }
        __syncthreads();
    }
}

// ---------------------------------------------------------------------------
// Kernel 3: implicit-GEMM conv via mma.sync (split-bf16, 3 terms)
// grid (y=128, b=8); CTA = 256 oc x 128 px; 8 warps (4M x 2N), warp tile 64x64
// K-loop: 36 steps = 9 taps x 4 chunks of 64 ch; 2-stage cp.async ring.
// Stage layout (96KB): Ah@0 (32K) Al@32K Bh@64K (16K) Bl@80K; SW128 rows of 128B.
// ---------------------------------------------------------------------------
#define NSTAGE 2
#define STAGE_BYTES 98304
#define SMEM_TOTAL (NSTAGE * STAGE_BYTES)

__global__ __launch_bounds__(256, 1)
void gemm_kernel(float* __restrict__ out) {
    extern __shared__ char smem[];
    const uint32_t sb = smem_u32(smem);
    const int tid  = threadIdx.x;
    const int lane = tid & 31;
    const int wid  = tid >> 5;
    const int warpM = wid >> 1;   // 0..3 (64 oc rows each)
    const int warpN = wid & 1;    // 0..1 (64 px cols each)
    const int y = blockIdx.x, b = blockIdx.y;

    // ---- producer constants ----
    // every thread: Ah row tid, Al row tid; threads<128: Bh row tid; >=128: Bl row tid-128
    const int brow = tid & 127;
    const bool isBh = tid < 128;
    const size_t abase = ((size_t)(b * 9) * CC + tid) * CC;

    auto issue = [&](int step, int buf) {
        const int tap = step >> 2, ck = step & 3;
        const uint32_t stg = sb + (uint32_t)buf * STAGE_BYTES;
        const size_t aoff = abase + (size_t)tap * CC * CC + ck * 64;
        const __nv_bfloat16* srcAh = g_Ahi + aoff;
        const __nv_bfloat16* srcAl = g_Alo + aoff;
        const int yy = y + tap / 3 - 1;
        const int xx = brow + tap % 3 - 1;
        const bool bv = (yy >= 0 && yy < HH && xx >= 0 && xx < WW);
        const size_t boff =
            ((size_t)((b * HH + (bv ? yy : 0)) * WW + (bv ? xx : 0))) * CC + ck * 64;
        const __nv_bfloat16* srcB = (isBh ? g_Fhi : g_Flo) + boff;
        const uint32_t bsz = bv ? 16u : 0u;
        const uint32_t bdst = stg + 65536u + (isBh ? 0u : 16384u);
#pragma unroll
        for (int j = 0; j < 8; ++j) {
            const uint32_t da = swz((uint32_t)tid * 128u + j * 16u);
            cpa16(stg + da,          srcAh + j * 8, 16u);
            cpa16(stg + 32768u + da, srcAl + j * 8, 16u);
            cpa16(bdst + swz((uint32_t)brow * 128u + j * 16u), srcB + j * 8, bsz);
        }
    };

    // ---- consumer address bases (pre-swizzle offsets within a stage) ----
    // A (x4): row = warpM*64 + m*16 + (lane&15); col16B = (lane>>4)
    const uint32_t aRowB = ((uint32_t)warpM * 64u + (lane & 15)) * 128u + ((lane >> 4) * 16u);
    // B (x4, two 8-col n-tiles per load): row = warpN*64 + np*16 + (lane>>4)*8 + (lane&7)
    const uint32_t bRowB = ((uint32_t)warpN * 64u + (lane >> 4) * 8u + (lane & 7)) * 128u
                           + (((lane >> 3) & 1) * 16u);

    float acc[4][8][4];
#pragma unroll
    for (int m = 0; m < 4; ++m)
#pragma unroll
        for (int n = 0; n < 8; ++n)
#pragma unroll
            for (int i = 0; i < 4; ++i) acc[m][n][i] = 0.f;

    issue(0, 0); cpa_commit();

#pragma unroll 1
    for (int s = 0; s < 36; ++s) {
        if (s + 1 < 36) issue(s + 1, (s + 1) & 1);
        cpa_commit();
        cpa_wait1();          // stage s copies complete (this thread)
        __syncthreads();      // all threads' copies complete

        const uint32_t stg = sb + (uint32_t)(s & 1) * STAGE_BYTES;

#pragma unroll
        for (int kk = 0; kk < 4; ++kk) {
            uint32_t Ah[4][4], Al[4][4];
#pragma unroll
            for (int m = 0; m < 4; ++m) {
                const uint32_t off = swz(aRowB + (uint32_t)m * 2048u + (uint32_t)kk * 32u);
                ldsm_x4(Ah[m][0], Ah[m][1], Ah[m][2], Ah[m][3], stg + off);
                ldsm_x4(Al[m][0], Al[m][1], Al[m][2], Al[m][3], stg + 32768u + off);
            }
#pragma unroll
            for (int np = 0; np < 4; ++np) {     // covers n-tiles 2np, 2np+1
                uint32_t Bh[4], Bl[4];
                const uint32_t off = swz(bRowB + (uint32_t)np * 2048u + (uint32_t)kk * 32u);
                ldsm_x4(Bh[0], Bh[1], Bh[2], Bh[3], stg + 65536u + off);
                ldsm_x4(Bl[0], Bl[1], Bl[2], Bl[3], stg + 81920u + off);
#pragma unroll
                for (int half = 0; half < 2; ++half) {
                    const int n = 2 * np + half;
                    const uint32_t* bh = &Bh[half * 2];
                    const uint32_t* bl = &Bl[half * 2];
#pragma unroll
                    for (int m = 0; m < 4; ++m) {
                        mma_bf16(acc[m][n], Ah[m], bh);
                        mma_bf16(acc[m][n], Ah[m], bl);
                        mma_bf16(acc[m][n], Al[m], bh);
                    }
                }
            }
        }
        __syncthreads();      // protect buffer before re-fill
    }

    // ---- epilogue ----
    const int r0 = warpM * 64 + (lane >> 2);
    const int xc = warpN * 64 + (lane & 3) * 2;
#pragma unroll
    for (int m = 0; m < 4; ++m) {
#pragma unroll
        for (int n = 0; n < 8; ++n) {
            float* p0 = out + (((size_t)(b * CC + r0 + m * 16) * HH + y) * WW) + xc + n * 8;
            float* p1 = p0 + (size_t)8 * HH * WW;
            *(float2*)p0 = make_float2(acc[m][n][0], acc[m][n][1]);
            *(float2*)p1 = make_float2(acc[m][n][2], acc[m][n][3]);
        }
    }
}

// ---------------------------------------------------------------------------
extern "C" void kernel_launch(void* const* d_in, const int* in_sizes, int n_in,
                              void* d_out, int out_size) {
    const float* fea    = (const float*)d_in[0];
    const float* nf     = (const float*)d_in[1];
    const float* mw     = (const float*)d_in[2];
    const float* mb     = (const float*)d_in[3];
    const float* weight = (const float*)d_in[4];
    float* out = (float*)d_out;

    cudaFuncSetAttribute(gemm_kernel, cudaFuncAttributeMaxDynamicSharedMemorySize, SMEM_TOTAL);

    style_kernel<<<BB, CC>>>(nf, mw, mb);
    modw_kernel<<<dim3(CC, BB), CC>>>(weight);
    tsplit_kernel<<<dim3(HH, BB), 256>>>(fea);
    gemm_kernel<<<dim3(HH, BB), 256, SMEM_TOTAL>>>(out);
}

// round 7
// speedup vs baseline: 1.2881x; 1.0658x over previous
#include <cuda_runtime.h>
#include <cuda_bf16.h>
#include <cstdint>

// Problem constants
#define BB 8
#define CC 256
#define HH 128
#define WW 128
#define ND 64

// ---------------------------------------------------------------------------
// Scratch (__device__ globals; no runtime allocation)
// ---------------------------------------------------------------------------
__device__ float g_style[BB * CC];
__device__ __align__(256) __nv_bfloat16 g_Ahi[BB * 9 * CC * CC];   // [b][tap][oc][i]
__device__ __align__(256) __nv_bfloat16 g_Alo[BB * 9 * CC * CC];
__device__ __align__(256) __nv_bfloat16 g_Fhi[(size_t)BB * HH * WW * CC];  // [b][y][x][c]
__device__ __align__(256) __nv_bfloat16 g_Flo[(size_t)BB * HH * WW * CC];

// ---------------------------------------------------------------------------
// PTX helpers (sm_80-era; compile on compute_103)
// ---------------------------------------------------------------------------
__device__ __forceinline__ uint32_t smem_u32(const void* p) {
    uint32_t a;
    asm("{ .reg .u64 t; cvta.to.shared.u64 t, %1; cvt.u32.u64 %0, t; }" : "=r"(a) : "l"(p));
    return a;
}
__device__ __forceinline__ void cpa16(uint32_t dst, const void* src, uint32_t bytes) {
    asm volatile("cp.async.cg.shared.global [%0], [%1], 16, %2;"
                 :: "r"(dst), "l"(src), "r"(bytes) : "memory");
}
__device__ __forceinline__ void cpa_commit() {
    asm volatile("cp.async.commit_group;" ::: "memory");
}
__device__ __forceinline__ void cpa_wait1() {
    asm volatile("cp.async.wait_group 1;" ::: "memory");
}
__device__ __forceinline__ uint32_t swz(uint32_t off) { return off ^ ((off >> 3) & 0x70); }

__device__ __forceinline__ void ldsm_x4(uint32_t& r0, uint32_t& r1, uint32_t& r2, uint32_t& r3,
                                        uint32_t addr) {
    asm volatile("ldmatrix.sync.aligned.m8n8.x4.shared.b16 {%0,%1,%2,%3}, [%4];"
                 : "=r"(r0), "=r"(r1), "=r"(r2), "=r"(r3) : "r"(addr));
}
__device__ __forceinline__ void mma_bf16(float* d, const uint32_t* a, const uint32_t* b) {
    asm volatile(
        "mma.sync.aligned.m16n8k16.row.col.f32.bf16.bf16.f32 "
        "{%0,%1,%2,%3}, {%4,%5,%6,%7}, {%8,%9}, {%0,%1,%2,%3};"
        : "+f"(d[0]), "+f"(d[1]), "+f"(d[2]), "+f"(d[3])
        : "r"(a[0]), "r"(a[1]), "r"(a[2]), "r"(a[3]), "r"(b[0]), "r"(b[1]));
}

// ---------------------------------------------------------------------------
// Kernel 0: style
// ---------------------------------------------------------------------------
__global__ void style_kernel(const float* __restrict__ nf,
                             const float* __restrict__ mw,
                             const float* __restrict__ mb) {
    int b = blockIdx.x, c = threadIdx.x;
    const float* nfb = nf + b * ND;
    const float* mwc = mw + c * ND;
    float s = 0.f;
#pragma unroll
    for (int d = 0; d < ND; ++d) s += nfb[d] * mwc[d];
    g_style[b * CC + c] = s + mb[c];
}

// ---------------------------------------------------------------------------
// Kernel 1: modulate + demod weights, split bf16, layout [b][tap][oc][i]
// ---------------------------------------------------------------------------
__global__ void modw_kernel(const float* __restrict__ weight) {
    int o = blockIdx.x, b = blockIdx.y, i = threadIdx.x;
    const float scale = 1.0f / 48.0f;
    float s = g_style[b * CC + i] * scale;
    const float* wp = weight + (o * CC + i) * 9;
    float v[9];
    float sq = 0.f;
#pragma unroll
    for (int k = 0; k < 9; ++k) { v[k] = wp[k] * s; sq += v[k] * v[k]; }

    __shared__ float red[8];
#pragma unroll
    for (int off = 16; off; off >>= 1) sq += __shfl_xor_sync(0xffffffffu, sq, off);
    if ((threadIdx.x & 31) == 0) red[threadIdx.x >> 5] = sq;
    __syncthreads();
    if (threadIdx.x < 8) {
        float t = red[threadIdx.x];
#pragma unroll
        for (int off = 4; off; off >>= 1) t += __shfl_xor_sync(0xffu, t, off);
        if (threadIdx.x == 0) red[0] = t;
    }
    __syncthreads();
    float demod = rsqrtf(red[0] + 1e-8f);
#pragma unroll
    for (int k = 0; k < 9; ++k) {
        float val = v[k] * demod;
        __nv_bfloat16 hi = __float2bfloat16(val);
        float lof = val - __bfloat162float(hi);
        size_t idx = ((size_t)((b * 9 + k) * CC) + o) * CC + i;
        g_Ahi[idx] = hi;
        g_Alo[idx] = __float2bfloat16(lof);
    }
}

// ---------------------------------------------------------------------------
// Kernel 2: fea NCHW -> [b][y][x][c] with bf16 hi/lo split
// ---------------------------------------------------------------------------
__global__ __launch_bounds__(256)
void tsplit_kernel(const float* __restrict__ fea) {
    int y = blockIdx.x, b = blockIdx.y;
    __shared__ float t[64][129];
    for (int cc = 0; cc < 4; ++cc) {
#pragma unroll
        for (int k = 0; k < 32; ++k) {
            int idx = threadIdx.x + k * 256;
            int cs = idx >> 7, x = idx & 127;
            t[cs][x] = fea[(((size_t)(b * CC + cc * 64 + cs)) * HH + y) * WW + x];
        }
        __syncthreads();
#pragma unroll
        for (int k = 0; k < 32; ++k) {
            int idx = threadIdx.x + k * 256;
            int c2 = idx & 63, x = idx >> 6;
            float v = t[c2][x];
            __nv_bfloat16 hi = __float2bfloat16(v);
            size_t o = ((size_t)((b * HH + y) * WW + x)) * CC + cc * 64 + c2;
            g_Fhi[o] = hi;
            g_Flo[o] = __float2bfloat16(v - __bfloat162float(hi));
        }
        __syncthreads();
    }
}

// ---------------------------------------------------------------------------
// Kernel 3: implicit-GEMM conv via mma.sync (split-bf16, 3 terms)
// grid (y=128, b=8); CTA = 256 oc x 128 px; 16 warps (8M x 2N), warp tile 32x64
// K-loop: 36 steps = 9 taps x 4 chunks of 64 ch; 2-stage cp.async ring.
// Stage (96KB): Ah@0 (32K) Al@32K Bh@64K (16K) Bl@80K; SW128 rows of 128B.
// ---------------------------------------------------------------------------
#define NSTAGE 2
#define STAGE_BYTES 98304
#define SMEM_TOTAL (NSTAGE * STAGE_BYTES)

__global__ __launch_bounds__(512, 1)
void gemm_kernel(float* __restrict__ out) {
    extern __shared__ char smem[];
    const uint32_t sb = smem_u32(smem);
    const int tid  = threadIdx.x;
    const int lane = tid & 31;
    const int wid  = tid >> 5;
    const int warpM = wid >> 1;   // 0..7 (32 oc rows each)
    const int warpN = wid & 1;    // 0..1 (64 px cols each)
    const int y = blockIdx.x, b = blockIdx.y;

    // ---- producer assignment ----
    // A: thread tid<256 -> Ah row tid (128B); tid>=256 -> Al row tid-256.
    // B: thread tid -> row (tid>>1) of Bh(if <128) / Bl(row-128), half tid&1 (64B).
    const int aRow = tid & 255;
    const bool isAh = tid < 256;
    const int bRowAll = tid >> 1;          // 0..255
    const int bRow = bRowAll & 127;        // pixel index
    const bool isBh = bRowAll < 128;
    const int bHalf = tid & 1;             // 64B half
    const size_t aRowBase = ((size_t)(b * 9) * CC + aRow) * CC;

    auto issue = [&](int step, int buf) {
        const int tap = step >> 2, ck = step & 3;
        const uint32_t stg = sb + (uint32_t)buf * STAGE_BYTES;
        // A row
        const size_t aoff = aRowBase + (size_t)tap * CC * CC + ck * 64;
        const __nv_bfloat16* srcA = (isAh ? g_Ahi : g_Alo) + aoff;
        const uint32_t adst = stg + (isAh ? 0u : 32768u);
#pragma unroll
        for (int j = 0; j < 8; ++j)
            cpa16(adst + swz((uint32_t)aRow * 128u + j * 16u), srcA + j * 8, 16u);
        // B half-row
        const int yy = y + tap / 3 - 1;
        const int xx = bRow + tap % 3 - 1;
        const bool bv = (yy >= 0 && yy < HH && xx >= 0 && xx < WW);
        const size_t boff = ((size_t)((b * HH + (bv ? yy : 0)) * WW + (bv ? xx : 0))) * CC
                            + ck * 64 + bHalf * 32;
        const __nv_bfloat16* srcB = (isBh ? g_Fhi : g_Flo) + boff;
        const uint32_t bsz = bv ? 16u : 0u;
        const uint32_t bdst = stg + 65536u + (isBh ? 0u : 16384u);
#pragma unroll
        for (int j = 0; j < 4; ++j)
            cpa16(bdst + swz((uint32_t)bRow * 128u + bHalf * 64u + j * 16u),
                  srcB + j * 8, bsz);
    };

    // ---- consumer address bases (pre-swizzle offsets within a stage) ----
    // A (x4): row = warpM*32 + m*16 + (lane&15); col16B = (lane>>4)
    const uint32_t aRowB = ((uint32_t)warpM * 32u + (lane & 15)) * 128u + ((lane >> 4) * 16u);
    // B (x4, 2 n-tiles per load): row = warpN*64 + np*16 + (lane>>4)*8 + (lane&7)
    const uint32_t bRowB = ((uint32_t)warpN * 64u + (lane >> 4) * 8u + (lane & 7)) * 128u
                           + (((lane >> 3) & 1) * 16u);

    float acc[2][8][4];
#pragma unroll
    for (int m = 0; m < 2; ++m)
#pragma unroll
        for (int n = 0; n < 8; ++n)
#pragma unroll
            for (int i = 0; i < 4; ++i) acc[m][n][i] = 0.f;

    issue(0, 0); cpa_commit();

#pragma unroll 1
    for (int s = 0; s < 36; ++s) {
        if (s + 1 < 36) issue(s + 1, (s + 1) & 1);
        cpa_commit();
        cpa_wait1();          // stage s copies complete (this thread)
        __syncthreads();      // all threads' copies complete

        const uint32_t stg = sb + (uint32_t)(s & 1) * STAGE_BYTES;

#pragma unroll
        for (int kk = 0; kk < 4; ++kk) {
            uint32_t Ah[2][4], Al[2][4], Bh[4][4], Bl[4][4];
#pragma unroll
            for (int m = 0; m < 2; ++m) {
                const uint32_t off = swz(aRowB + (uint32_t)m * 2048u + (uint32_t)kk * 32u);
                ldsm_x4(Ah[m][0], Ah[m][1], Ah[m][2], Ah[m][3], stg + off);
                ldsm_x4(Al[m][0], Al[m][1], Al[m][2], Al[m][3], stg + 32768u + off);
            }
#pragma unroll
            for (int np = 0; np < 4; ++np) {
                const uint32_t off = swz(bRowB + (uint32_t)np * 2048u + (uint32_t)kk * 32u);
                ldsm_x4(Bh[np][0], Bh[np][1], Bh[np][2], Bh[np][3], stg + 65536u + off);
                ldsm_x4(Bl[np][0], Bl[np][1], Bl[np][2], Bl[np][3], stg + 81920u + off);
            }
#pragma unroll
            for (int m = 0; m < 2; ++m)
#pragma unroll
                for (int n = 0; n < 8; ++n) {
                    const uint32_t* bh = &Bh[n >> 1][(n & 1) * 2];
                    const uint32_t* bl = &Bl[n >> 1][(n & 1) * 2];
                    mma_bf16(acc[m][n], Ah[m], bh);
                    mma_bf16(acc[m][n], Ah[m], bl);
                    mma_bf16(acc[m][n], Al[m], bh);
                }
        }
        __syncthreads();      // protect buffer before re-fill
    }

    // ---- epilogue ----
    const int r0 = warpM * 32 + (lane >> 2);
    const int xc = warpN * 64 + (lane & 3) * 2;
#pragma unroll
    for (int m = 0; m < 2; ++m) {
#pragma unroll
        for (int n = 0; n < 8; ++n) {
            float* p0 = out + (((size_t)(b * CC + r0 + m * 16) * HH + y) * WW) + xc + n * 8;
            float* p1 = p0 + (size_t)8 * HH * WW;
            *(float2*)p0 = make_float2(acc[m][n][0], acc[m][n][1]);
            *(float2*)p1 = make_float2(acc[m][n][2], acc[m][n][3]);
        }
    }
}

// ---------------------------------------------------------------------------
extern "C" void kernel_launch(void* const* d_in, const int* in_sizes, int n_in,
                              void* d_out, int out_size) {
    const float* fea    = (const float*)d_in[0];
    const float* nf     = (const float*)d_in[1];
    const float* mw     = (const float*)d_in[2];
    const float* mb     = (const float*)d_in[3];
    const float* weight = (const float*)d_in[4];
    float* out = (float*)d_out;

    cudaFuncSetAttribute(gemm_kernel, cudaFuncAttributeMaxDynamicSharedMemorySize, SMEM_TOTAL);

    style_kernel<<<BB, CC>>>(nf, mw, mb);
    modw_kernel<<<dim3(CC, BB), CC>>>(weight);
    tsplit_kernel<<<dim3(HH, BB), 256>>>(fea);
    gemm_kernel<<<dim3(HH, BB), 512, SMEM_TOTAL>>>(out);
}

// round 8
// speedup vs baseline: 2.9786x; 2.3125x over previous
#include <cuda_runtime.h>
#include <cuda_bf16.h>
#include <cuda_fp16.h>
#include <cstdint>

// Problem constants
#define BB 8
#define CC 256
#define HH 128
#define WW 128
#define ND 64

// ---------------------------------------------------------------------------
// Scratch (__device__ globals; no runtime allocation)
// ---------------------------------------------------------------------------
__device__ float g_style[BB * CC];
__device__ __align__(256) __half g_Af[BB * 9 * CC * CC];            // [b][tap][oc][i]
__device__ __align__(256) __half g_Ff[(size_t)BB * HH * WW * CC];   // [b][y][x][c]

// ---------------------------------------------------------------------------
// PTX helpers (sm_80-era; compile on compute_103)
// ---------------------------------------------------------------------------
__device__ __forceinline__ uint32_t smem_u32(const void* p) {
    uint32_t a;
    asm("{ .reg .u64 t; cvta.to.shared.u64 t, %1; cvt.u32.u64 %0, t; }" : "=r"(a) : "l"(p));
    return a;
}
__device__ __forceinline__ void cpa16(uint32_t dst, const void* src, uint32_t bytes) {
    asm volatile("cp.async.cg.shared.global [%0], [%1], 16, %2;"
                 :: "r"(dst), "l"(src), "r"(bytes) : "memory");
}
__device__ __forceinline__ void cpa_commit() {
    asm volatile("cp.async.commit_group;" ::: "memory");
}
__device__ __forceinline__ void cpa_wait2() {
    asm volatile("cp.async.wait_group 2;" ::: "memory");
}
__device__ __forceinline__ uint32_t swz(uint32_t off) { return off ^ ((off >> 3) & 0x70); }

__device__ __forceinline__ void ldsm_x4(uint32_t& r0, uint32_t& r1, uint32_t& r2, uint32_t& r3,
                                        uint32_t addr) {
    asm volatile("ldmatrix.sync.aligned.m8n8.x4.shared.b16 {%0,%1,%2,%3}, [%4];"
                 : "=r"(r0), "=r"(r1), "=r"(r2), "=r"(r3) : "r"(addr));
}
__device__ __forceinline__ void mma_fp16(float* d, const uint32_t* a, const uint32_t* b) {
    asm volatile(
        "mma.sync.aligned.m16n8k16.row.col.f32.f16.f16.f32 "
        "{%0,%1,%2,%3}, {%4,%5,%6,%7}, {%8,%9}, {%0,%1,%2,%3};"
        : "+f"(d[0]), "+f"(d[1]), "+f"(d[2]), "+f"(d[3])
        : "r"(a[0]), "r"(a[1]), "r"(a[2]), "r"(a[3]), "r"(b[0]), "r"(b[1]));
}

// ---------------------------------------------------------------------------
// Kernel 0: style
// ---------------------------------------------------------------------------
__global__ void style_kernel(const float* __restrict__ nf,
                             const float* __restrict__ mw,
                             const float* __restrict__ mb) {
    int b = blockIdx.x, c = threadIdx.x;
    const float* nfb = nf + b * ND;
    const float* mwc = mw + c * ND;
    float s = 0.f;
#pragma unroll
    for (int d = 0; d < ND; ++d) s += nfb[d] * mwc[d];
    g_style[b * CC + c] = s + mb[c];
}

// ---------------------------------------------------------------------------
// Kernel 1: modulate + demod weights -> fp16, layout [b][tap][oc][i]
// ---------------------------------------------------------------------------
__global__ void modw_kernel(const float* __restrict__ weight) {
    int o = blockIdx.x, b = blockIdx.y, i = threadIdx.x;
    const float scale = 1.0f / 48.0f;
    float s = g_style[b * CC + i] * scale;
    const float* wp = weight + (o * CC + i) * 9;
    float v[9];
    float sq = 0.f;
#pragma unroll
    for (int k = 0; k < 9; ++k) { v[k] = wp[k] * s; sq += v[k] * v[k]; }

    __shared__ float red[8];
#pragma unroll
    for (int off = 16; off; off >>= 1) sq += __shfl_xor_sync(0xffffffffu, sq, off);
    if ((threadIdx.x & 31) == 0) red[threadIdx.x >> 5] = sq;
    __syncthreads();
    if (threadIdx.x < 8) {
        float t = red[threadIdx.x];
#pragma unroll
        for (int off = 4; off; off >>= 1) t += __shfl_xor_sync(0xffu, t, off);
        if (threadIdx.x == 0) red[0] = t;
    }
    __syncthreads();
    float demod = rsqrtf(red[0] + 1e-8f);
#pragma unroll
    for (int k = 0; k < 9; ++k) {
        size_t idx = ((size_t)((b * 9 + k) * CC) + o) * CC + i;
        g_Af[idx] = __float2half(v[k] * demod);
    }
}

// ---------------------------------------------------------------------------
// Kernel 2: fea NCHW -> [b][y][x][c] fp16
// ---------------------------------------------------------------------------
__global__ __launch_bounds__(256)
void tsplit_kernel(const float* __restrict__ fea) {
    int y = blockIdx.x, b = blockIdx.y;
    __shared__ float t[64][129];
    for (int cc = 0; cc < 4; ++cc) {
#pragma unroll
        for (int k = 0; k < 32; ++k) {
            int idx = threadIdx.x + k * 256;
            int cs = idx >> 7, x = idx & 127;
            t[cs][x] = fea[(((size_t)(b * CC + cc * 64 + cs)) * HH + y) * WW + x];
        }
        __syncthreads();
#pragma unroll
        for (int k = 0; k < 32; ++k) {
            int idx = threadIdx.x + k * 256;
            int c2 = idx & 63, x = idx >> 6;
            size_t o = ((size_t)((b * HH + y) * WW + x)) * CC + cc * 64 + c2;
            g_Ff[o] = __float2half(t[c2][x]);
        }
        __syncthreads();
    }
}

// ---------------------------------------------------------------------------
// Kernel 3: implicit-GEMM conv via mma.sync, pure fp16 operands, f32 accum.
// grid (y=128, b=8); CTA = 256 oc x 128 px; 16 warps (8M x 2N), warp tile 32x64
// K-loop: 36 steps = 9 taps x 4 chunks of 64 ch; 3-stage cp.async ring.
// Stage (48KB): A@0 (32KB: 256 rows x 128B) B@32K (16KB: 128 rows x 128B), SW128.
// ---------------------------------------------------------------------------
#define NSTAGE 3
#define STAGE_BYTES 49152
#define SMEM_TOTAL (NSTAGE * STAGE_BYTES)

__global__ __launch_bounds__(512, 1)
void gemm_kernel(float* __restrict__ out) {
    extern __shared__ char smem[];
    const uint32_t sb = smem_u32(smem);
    const int tid  = threadIdx.x;
    const int lane = tid & 31;
    const int wid  = tid >> 5;
    const int warpM = wid >> 1;   // 0..7 (32 oc rows each)
    const int warpN = wid & 1;    // 0..1 (64 px cols each)
    const int y = blockIdx.x, b = blockIdx.y;

    // ---- producer assignment ----
    // threads 0-255: A row tid (128B = 8 cpa16)
    // threads 256-511: B half-row: row (tid-256)>>1, half (tid&1) (64B = 4 cpa16)
    const bool isA = tid < 256;
    const int aRow = tid & 255;
    const int bRow = (tid >> 1) & 127;
    const int bHalf = tid & 1;
    const size_t aRowBase = ((size_t)(b * 9) * CC + aRow) * CC;

    auto issue = [&](int step, int buf) {
        const int tap = step >> 2, ck = step & 3;
        const uint32_t stg = sb + (uint32_t)buf * STAGE_BYTES;
        if (isA) {
            const __half* srcA = g_Af + aRowBase + (size_t)tap * CC * CC + ck * 64;
#pragma unroll
            for (int j = 0; j < 8; ++j)
                cpa16(stg + swz((uint32_t)aRow * 128u + j * 16u), srcA + j * 8, 16u);
        } else {
            const int yy = y + tap / 3 - 1;
            const int xx = bRow + tap % 3 - 1;
            const bool bv = (yy >= 0 && yy < HH && xx >= 0 && xx < WW);
            const size_t boff = ((size_t)((b * HH + (bv ? yy : 0)) * WW + (bv ? xx : 0))) * CC
                                + ck * 64 + bHalf * 32;
            const __half* srcB = g_Ff + boff;
            const uint32_t bsz = bv ? 16u : 0u;
#pragma unroll
            for (int j = 0; j < 4; ++j)
                cpa16(stg + 32768u + swz((uint32_t)bRow * 128u + bHalf * 64u + j * 16u),
                      srcB + j * 8, bsz);
        }
    };

    // ---- consumer address bases (pre-swizzle offsets within a stage) ----
    // A (x4): row = warpM*32 + m*16 + (lane&15); col16B = (lane>>4)
    const uint32_t aRowB = ((uint32_t)warpM * 32u + (lane & 15)) * 128u + ((lane >> 4) * 16u);
    // B (x4, 2 n-tiles per load): row = warpN*64 + np*16 + (lane>>4)*8 + (lane&7)
    const uint32_t bRowB = ((uint32_t)warpN * 64u + (lane >> 4) * 8u + (lane & 7)) * 128u
                           + (((lane >> 3) & 1) * 16u);

    float acc[2][8][4];
#pragma unroll
    for (int m = 0; m < 2; ++m)
#pragma unroll
        for (int n = 0; n < 8; ++n)
#pragma unroll
            for (int i = 0; i < 4; ++i) acc[m][n][i] = 0.f;

    issue(0, 0); cpa_commit();
    issue(1, 1); cpa_commit();

#pragma unroll 1
    for (int s = 0; s < 36; ++s) {
        if (s + 2 < 36) issue(s + 2, (s + 2) % NSTAGE);
        cpa_commit();
        cpa_wait2();          // stage s copies complete (this thread)
        __syncthreads();      // all threads' copies complete

        const uint32_t stg = sb + (uint32_t)(s % NSTAGE) * STAGE_BYTES;

#pragma unroll
        for (int kk = 0; kk < 4; ++kk) {
            uint32_t A[2][4], B[4][4];
#pragma unroll
            for (int m = 0; m < 2; ++m) {
                const uint32_t off = swz(aRowB + (uint32_t)m * 2048u + (uint32_t)kk * 32u);
                ldsm_x4(A[m][0], A[m][1], A[m][2], A[m][3], stg + off);
            }
#pragma unroll
            for (int np = 0; np < 4; ++np) {
                const uint32_t off = swz(bRowB + (uint32_t)np * 2048u + (uint32_t)kk * 32u);
                ldsm_x4(B[np][0], B[np][1], B[np][2], B[np][3], stg + 32768u + off);
            }
#pragma unroll
            for (int m = 0; m < 2; ++m)
#pragma unroll
                for (int n = 0; n < 8; ++n)
                    mma_fp16(acc[m][n], A[m], &B[n >> 1][(n & 1) * 2]);
        }
        __syncthreads();      // protect buffer before re-fill
    }

    // ---- epilogue ----
    const int r0 = warpM * 32 + (lane >> 2);
    const int xc = warpN * 64 + (lane & 3) * 2;
#pragma unroll
    for (int m = 0; m < 2; ++m) {
#pragma unroll
        for (int n = 0; n < 8; ++n) {
            float* p0 = out + (((size_t)(b * CC + r0 + m * 16) * HH + y) * WW) + xc + n * 8;
            float* p1 = p0 + (size_t)8 * HH * WW;
            *(float2*)p0 = make_float2(acc[m][n][0], acc[m][n][1]);
            *(float2*)p1 = make_float2(acc[m][n][2], acc[m][n][3]);
        }
    }
}

// ---------------------------------------------------------------------------
extern "C" void kernel_launch(void* const* d_in, const int* in_sizes, int n_in,
                              void* d_out, int out_size) {
    const float* fea    = (const float*)d_in[0];
    const float* nf     = (const float*)d_in[1];
    const float* mw     = (const float*)d_in[2];
    const float* mb     = (const float*)d_in[3];
    const float* weight = (const float*)d_in[4];
    float* out = (float*)d_out;

    cudaFuncSetAttribute(gemm_kernel, cudaFuncAttributeMaxDynamicSharedMemorySize, SMEM_TOTAL);

    style_kernel<<<BB, CC>>>(nf, mw, mb);
    modw_kernel<<<dim3(CC, BB), CC>>>(weight);
    tsplit_kernel<<<dim3(HH, BB), 256>>>(fea);
    gemm_kernel<<<dim3(HH, BB), 512, SMEM_TOTAL>>>(out);
}

// round 9
// speedup vs baseline: 3.0552x; 1.0257x over previous
#include <cuda_runtime.h>
#include <cuda_bf16.h>
#include <cuda_fp16.h>
#include <cstdint>

// Problem constants
#define BB 8
#define CC 256
#define HH 128
#define WW 128
#define ND 64

// ---------------------------------------------------------------------------
// Scratch (__device__ globals; no runtime allocation)
// ---------------------------------------------------------------------------
__device__ float g_style[BB * CC];
__device__ __align__(256) __half g_Af[BB * 9 * CC * CC];            // [b][tap][oc][i]
__device__ __align__(256) __half g_Ff[(size_t)BB * HH * WW * CC];   // [b][y][x][c]

// ---------------------------------------------------------------------------
// PTX helpers (sm_80-era; compile on compute_103)
// ---------------------------------------------------------------------------
__device__ __forceinline__ uint32_t smem_u32(const void* p) {
    uint32_t a;
    asm("{ .reg .u64 t; cvta.to.shared.u64 t, %1; cvt.u32.u64 %0, t; }" : "=r"(a) : "l"(p));
    return a;
}
__device__ __forceinline__ void cpa16(uint32_t dst, const void* src, uint32_t bytes) {
    asm volatile("cp.async.cg.shared.global [%0], [%1], 16, %2;"
                 :: "r"(dst), "l"(src), "r"(bytes) : "memory");
}
__device__ __forceinline__ void cpa_commit() {
    asm volatile("cp.async.commit_group;" ::: "memory");
}
__device__ __forceinline__ void cpa_wait1() {
    asm volatile("cp.async.wait_group 1;" ::: "memory");
}
__device__ __forceinline__ uint32_t swz(uint32_t off) { return off ^ ((off >> 3) & 0x70); }

__device__ __forceinline__ void ldsm_x4(uint32_t& r0, uint32_t& r1, uint32_t& r2, uint32_t& r3,
                                        uint32_t addr) {
    asm volatile("ldmatrix.sync.aligned.m8n8.x4.shared.b16 {%0,%1,%2,%3}, [%4];"
                 : "=r"(r0), "=r"(r1), "=r"(r2), "=r"(r3) : "r"(addr));
}
__device__ __forceinline__ void mma_fp16(float* d, const uint32_t* a, const uint32_t* b) {
    asm volatile(
        "mma.sync.aligned.m16n8k16.row.col.f32.f16.f16.f32 "
        "{%0,%1,%2,%3}, {%4,%5,%6,%7}, {%8,%9}, {%0,%1,%2,%3};"
        : "+f"(d[0]), "+f"(d[1]), "+f"(d[2]), "+f"(d[3])
        : "r"(a[0]), "r"(a[1]), "r"(a[2]), "r"(a[3]), "r"(b[0]), "r"(b[1]));
}

// ---------------------------------------------------------------------------
// Kernel 0: style
// ---------------------------------------------------------------------------
__global__ void style_kernel(const float* __restrict__ nf,
                             const float* __restrict__ mw,
                             const float* __restrict__ mb) {
    int b = blockIdx.x, c = threadIdx.x;
    const float* nfb = nf + b * ND;
    const float* mwc = mw + c * ND;
    float s = 0.f;
#pragma unroll
    for (int d = 0; d < ND; ++d) s += nfb[d] * mwc[d];
    g_style[b * CC + c] = s + mb[c];
}

// ---------------------------------------------------------------------------
// Kernel 1: modulate + demod weights -> fp16, layout [b][tap][oc][i]
// ---------------------------------------------------------------------------
__global__ void modw_kernel(const float* __restrict__ weight) {
    int o = blockIdx.x, b = blockIdx.y, i = threadIdx.x;
    const float scale = 1.0f / 48.0f;
    float s = g_style[b * CC + i] * scale;
    const float* wp = weight + (o * CC + i) * 9;
    float v[9];
    float sq = 0.f;
#pragma unroll
    for (int k = 0; k < 9; ++k) { v[k] = wp[k] * s; sq += v[k] * v[k]; }

    __shared__ float red[8];
#pragma unroll
    for (int off = 16; off; off >>= 1) sq += __shfl_xor_sync(0xffffffffu, sq, off);
    if ((threadIdx.x & 31) == 0) red[threadIdx.x >> 5] = sq;
    __syncthreads();
    if (threadIdx.x < 8) {
        float t = red[threadIdx.x];
#pragma unroll
        for (int off = 4; off; off >>= 1) t += __shfl_xor_sync(0xffu, t, off);
        if (threadIdx.x == 0) red[0] = t;
    }
    __syncthreads();
    float demod = rsqrtf(red[0] + 1e-8f);
#pragma unroll
    for (int k = 0; k < 9; ++k) {
        size_t idx = ((size_t)((b * 9 + k) * CC) + o) * CC + i;
        g_Af[idx] = __float2half(v[k] * demod);
    }
}

// ---------------------------------------------------------------------------
// Kernel 2: fea NCHW -> [b][y][x][c] fp16
// ---------------------------------------------------------------------------
__global__ __launch_bounds__(256)
void tsplit_kernel(const float* __restrict__ fea) {
    int y = blockIdx.x, b = blockIdx.y;
    __shared__ float t[64][129];
    for (int cc = 0; cc < 4; ++cc) {
#pragma unroll
        for (int k = 0; k < 32; ++k) {
            int idx = threadIdx.x + k * 256;
            int cs = idx >> 7, x = idx & 127;
            t[cs][x] = fea[(((size_t)(b * CC + cc * 64 + cs)) * HH + y) * WW + x];
        }
        __syncthreads();
#pragma unroll
        for (int k = 0; k < 32; ++k) {
            int idx = threadIdx.x + k * 256;
            int c2 = idx & 63, x = idx >> 6;
            size_t o = ((size_t)((b * HH + y) * WW + x)) * CC + cc * 64 + c2;
            g_Ff[o] = __float2half(t[c2][x]);
        }
        __syncthreads();
    }
}

// ---------------------------------------------------------------------------
// Kernel 3: implicit-GEMM conv via mma.sync, fp16 operands, f32 accum.
// grid (y=128, b=8); CTA = 256 oc x 128 px; 16 warps (8M x 2N), warp tile 32x64
// K-loop: 18 steps = 9 taps x 2 half-chunks of 128 ch; 2-stage cp.async ring.
// Stage (96KB): A0@0 A1@32K (each 256 rows x 128B) B0@64K B1@80K (128 x 128B).
// ---------------------------------------------------------------------------
#define NSTAGE 2
#define STAGE_BYTES 98304
#define SMEM_TOTAL (NSTAGE * STAGE_BYTES)

__global__ __launch_bounds__(512, 1)
void gemm_kernel(float* __restrict__ out) {
    extern __shared__ char smem[];
    const uint32_t sb = smem_u32(smem);
    const int tid  = threadIdx.x;
    const int lane = tid & 31;
    const int wid  = tid >> 5;
    const int warpM = wid >> 1;   // 0..7 (32 oc rows each)
    const int warpN = wid & 1;    // 0..1 (64 px cols each)
    const int y = blockIdx.x, b = blockIdx.y;

    // ---- producer assignment ----
    // threads 0-255: A row tid; per step 2 sub-chunks x 8 cpa16.
    // threads 256-511: B half-row; per step 2 sub-chunks x 4 cpa16.
    const bool isA = tid < 256;
    const int aRow = tid & 255;
    const int bRow = (tid >> 1) & 127;
    const int bHalf = tid & 1;
    const size_t aRowBase = ((size_t)(b * 9) * CC + aRow) * CC;

    auto issue = [&](int step, int buf) {
        const int tap = step >> 1, ckh = step & 1;     // 128-channel half
        const uint32_t stg = sb + (uint32_t)buf * STAGE_BYTES;
        if (isA) {
            const __half* srcA = g_Af + aRowBase + (size_t)tap * CC * CC + ckh * 128;
#pragma unroll
            for (int sub = 0; sub < 2; ++sub)
#pragma unroll
                for (int j = 0; j < 8; ++j)
                    cpa16(stg + (uint32_t)sub * 32768u + swz((uint32_t)aRow * 128u + j * 16u),
                          srcA + sub * 64 + j * 8, 16u);
        } else {
            const int yy = y + tap / 3 - 1;
            const int xx = bRow + tap % 3 - 1;
            const bool bv = (yy >= 0 && yy < HH && xx >= 0 && xx < WW);
            const size_t boff = ((size_t)((b * HH + (bv ? yy : 0)) * WW + (bv ? xx : 0))) * CC
                                + ckh * 128 + bHalf * 32;
            const __half* srcB = g_Ff + boff;
            const uint32_t bsz = bv ? 16u : 0u;
#pragma unroll
            for (int sub = 0; sub < 2; ++sub)
#pragma unroll
                for (int j = 0; j < 4; ++j)
                    cpa16(stg + 65536u + (uint32_t)sub * 16384u
                              + swz((uint32_t)bRow * 128u + bHalf * 64u + j * 16u),
                          srcB + sub * 64 + j * 8, bsz);
        }
    };

    // ---- consumer address bases (pre-swizzle offsets within a sub-chunk) ----
    // A (x4): row = warpM*32 + m*16 + (lane&15); col16B = (lane>>4)
    const uint32_t aRowB = ((uint32_t)warpM * 32u + (lane & 15)) * 128u + ((lane >> 4) * 16u);
    // B (x4, 2 n-tiles per load): row = warpN*64 + np*16 + (lane>>4)*8 + (lane&7)
    const uint32_t bRowB = ((uint32_t)warpN * 64u + (lane >> 4) * 8u + (lane & 7)) * 128u
                           + (((lane >> 3) & 1) * 16u);

    float acc[2][8][4];
#pragma unroll
    for (int m = 0; m < 2; ++m)
#pragma unroll
        for (int n = 0; n < 8; ++n)
#pragma unroll
            for (int i = 0; i < 4; ++i) acc[m][n][i] = 0.f;

    issue(0, 0); cpa_commit();

#pragma unroll 1
    for (int s = 0; s < 18; ++s) {
        if (s + 1 < 18) issue(s + 1, (s + 1) & 1);
        cpa_commit();
        cpa_wait1();          // stage s copies complete (this thread)
        __syncthreads();      // all threads' copies complete

        const uint32_t stg = sb + (uint32_t)(s & 1) * STAGE_BYTES;

#pragma unroll
        for (int kk = 0; kk < 8; ++kk) {
            const uint32_t aSub = stg + (uint32_t)(kk >> 2) * 32768u;
            const uint32_t bSub = stg + 65536u + (uint32_t)(kk >> 2) * 16384u;
            const int k4 = kk & 3;
            uint32_t A[2][4], B[4][4];
#pragma unroll
            for (int m = 0; m < 2; ++m) {
                const uint32_t off = swz(aRowB + (uint32_t)m * 2048u + (uint32_t)k4 * 32u);
                ldsm_x4(A[m][0], A[m][1], A[m][2], A[m][3], aSub + off);
            }
#pragma unroll
            for (int np = 0; np < 4; ++np) {
                const uint32_t off = swz(bRowB + (uint32_t)np * 2048u + (uint32_t)k4 * 32u);
                ldsm_x4(B[np][0], B[np][1], B[np][2], B[np][3], bSub + off);
            }
#pragma unroll
            for (int m = 0; m < 2; ++m)
#pragma unroll
                for (int n = 0; n < 8; ++n)
                    mma_fp16(acc[m][n], A[m], &B[n >> 1][(n & 1) * 2]);
        }
        __syncthreads();      // protect buffer before re-fill
    }

    // ---- epilogue ----
    const int r0 = warpM * 32 + (lane >> 2);
    const int xc = warpN * 64 + (lane & 3) * 2;
#pragma unroll
    for (int m = 0; m < 2; ++m) {
#pragma unroll
        for (int n = 0; n < 8; ++n) {
            float* p0 = out + (((size_t)(b * CC + r0 + m * 16) * HH + y) * WW) + xc + n * 8;
            float* p1 = p0 + (size_t)8 * HH * WW;
            *(float2*)p0 = make_float2(acc[m][n][0], acc[m][n][1]);
            *(float2*)p1 = make_float2(acc[m][n][2], acc[m][n][3]);
        }
    }
}

// ---------------------------------------------------------------------------
extern "C" void kernel_launch(void* const* d_in, const int* in_sizes, int n_in,
                              void* d_out, int out_size) {
    const float* fea    = (const float*)d_in[0];
    const float* nf     = (const float*)d_in[1];
    const float* mw     = (const float*)d_in[2];
    const float* mb     = (const float*)d_in[3];
    const float* weight = (const float*)d_in[4];
    float* out = (float*)d_out;

    cudaFuncSetAttribute(gemm_kernel, cudaFuncAttributeMaxDynamicSharedMemorySize, SMEM_TOTAL);

    style_kernel<<<BB, CC>>>(nf, mw, mb);
    modw_kernel<<<dim3(CC, BB), CC>>>(weight);
    tsplit_kernel<<<dim3(HH, BB), 256>>>(fea);
    gemm_kernel<<<dim3(HH, BB), 512, SMEM_TOTAL>>>(out);
}